// round 8
// baseline (speedup 1.0000x reference)
#include <cuda_runtime.h>
#include <math.h>

typedef unsigned long long ull;

#define N_NODES 1024
#define E_EDGES 32768
#define EE_PAIRS 262144
#define CS 384
#define CZ 128
#define CG 16
#define NH 4
#define NR 64
#define LUT_N 8192
#define LUT_SCALE 256.0f
#define CAP1 64
#define CAP2 768

#define MMA_SMEM ((64 + 128) * 132 * 4)

// ---------------- scratch ---------------------------------------------------
__device__ float d_nl[N_NODES * CG];
__device__ float d_nr[N_NODES * CG];
__device__ float d_q[E_EDGES * CZ];
__device__ float d_k[E_EDGES * CZ];
__device__ float d_v[E_EDGES * CZ];
__device__ float d_og[E_EDGES * CZ];
__device__ float d_attn[(size_t)E_EDGES * CAP1 * NH];
__device__ float d_gupd[E_EDGES * CZ];
__device__ float d_lut[LUT_N * CZ];
__device__ int   d_cnt[E_EDGES];
__device__ int   d_cnt2[N_NODES];
__device__ int   d_src[E_EDGES * CAP1];
__device__ int4  d_rec[N_NODES * CAP2];

// ---------------- helpers ----------------------------------------------------
__device__ __forceinline__ ull pk2(float lo, float hi) {
    ull r;
    asm("mov.b64 %0, {%1, %2};" : "=l"(r) : "f"(lo), "f"(hi));
    return r;
}
__device__ __forceinline__ ull pkdup(float v) { return pk2(v, v); }
__device__ __forceinline__ void upk2(ull p, float& lo, float& hi) {
    asm("mov.b64 {%0, %1}, %2;" : "=f"(lo), "=f"(hi) : "l"(p));
}
__device__ __forceinline__ ull ffma2(ull a, ull b, ull c) {
    ull d;
    asm("fma.rn.f32x2 %0, %1, %2, %3;" : "=l"(d) : "l"(a), "l"(b), "l"(c));
    return d;
}
__device__ __forceinline__ float tf32r(float f) {
    unsigned u;
    asm("cvt.rna.tf32.f32 %0, %1;" : "=r"(u) : "f"(f));
    return __uint_as_float(u);
}
__device__ __forceinline__ float sigmoid_fast(float x) {
    float x2 = x * x;
    float s = 0.5f + x * (0.25f + x2 * (-2.0833334e-2f + x2 * 2.0833334e-3f));
    if (fabsf(x) > 0.7f) s = 1.f / (1.f + __expf(-x));
    return s;
}

// ---------------- K0: zero counters -------------------------------------------
__global__ void k_init() {
    int i = blockIdx.x * blockDim.x + threadIdx.x;
    for (; i < E_EDGES; i += gridDim.x * blockDim.x) {
        d_cnt[i] = 0;
        if (i < N_NODES) d_cnt2[i] = 0;
    }
}

// ---------------- K1: fused nlr + bucket-build + lut ---------------------------
// blocks [0,1024): nlr   [1024,2048): build   [2048,2176): lut
__global__ __launch_bounds__(256) void k_misc(
    const float* __restrict__ nf,
    const float* __restrict__ Wnl, const float* __restrict__ bnl,
    const float* __restrict__ Wnr, const float* __restrict__ bnr,
    const int* __restrict__ eidx, const int* __restrict__ eeidx,
    const float* __restrict__ Wdb, const float* __restrict__ bdb) {
    int b = blockIdx.x, t = threadIdx.x;
    if (b < 1024) {
        __shared__ float s_nf[CS];
        int n = b;
        for (int i = t; i < CS; i += 256) s_nf[i] = nf[n * CS + i];
        __syncthreads();
        if (t < CG) {
            float a = bnl[t];
            for (int k = 0; k < CS; k++) a += s_nf[k] * Wnl[k * CG + t];
            d_nl[n * CG + t] = a;
        } else if (t < 2 * CG) {
            int c = t - CG;
            float a = bnr[c];
            for (int k = 0; k < CS; k++) a += s_nf[k] * Wnr[k * CG + c];
            d_nr[n * CG + c] = a;
        }
    } else if (b < 2048) {
        int ee = (b - 1024) * 256 + t;
        int e0 = eeidx[ee];
        int e1 = eeidx[EE_PAIRS + ee];
        int p = atomicAdd(&d_cnt[e1], 1);
        p = p < CAP1 ? p : CAP1 - 1;
        int slot = e1 * CAP1 + p;
        d_src[slot] = e0;
        int n2 = eidx[e0];
        int n1 = eidx[e1];
        int p2 = atomicAdd(&d_cnt2[n2], 1);
        p2 = p2 < CAP2 ? p2 : CAP2 - 1;
        d_rec[n2 * CAP2 + p2] = make_int4(e0, e1, n1, slot);
    } else {
        __shared__ float s_w[NR][CZ];
        __shared__ float s_rbf[2][NR];
        int blk = b - 2048;
        int c = t & 127, half = t >> 7;
        for (int i = t; i < NR * CZ; i += 256) ((float*)s_w)[i] = Wdb[i];
        float bd = bdb[c];
        __syncthreads();
        const float MU_STEP = 20.f / 63.f;
        const float SIG_INV = 3.2f;
        for (int row = 0; row < 64; row += 2) {
            int dI = blk * 64 + row + half;
            float dist = (float)dI * (1.0f / LUT_SCALE);
            if (c < NR) {
                float tt = (dist - (float)c * MU_STEP) * SIG_INV;
                s_rbf[half][c] = __expf(-tt * tt);
            }
            __syncthreads();
            float a = bd;
#pragma unroll 16
            for (int r = 0; r < NR; r++) a += s_rbf[half][r] * s_w[r][c];
            d_lut[dI * CZ + c] = a;
            __syncthreads();
        }
    }
}

// ---------------- generic 64x128 tf32 MMA tile (optional fused LN on A) --------
template <bool SIG, bool LN>
__device__ __forceinline__ void mma_tile(
    const float* __restrict__ Ag, const float* __restrict__ lng,
    const float* __restrict__ lnb,
    const float* __restrict__ W, int wstride,
    const float* __restrict__ bias, float* __restrict__ dst, int eb) {
    extern __shared__ float sm[];
    float* As = sm;
    float* Bs = sm + 64 * 132;
    int t = threadIdx.x;

    const float* Asrc = Ag + (size_t)eb * 64 * CZ;
    if (LN) {
        // 4 threads per row; thread covers 32 consecutive cols
        int row = t >> 2, seg = t & 3;
        const float* src = Asrc + row * CZ + seg * 32;
        float4 x[8];
        float s = 0.f, ss = 0.f;
#pragma unroll
        for (int j = 0; j < 8; j++) {
            x[j] = *(const float4*)(src + j * 4);
            s += x[j].x + x[j].y + x[j].z + x[j].w;
            ss += x[j].x * x[j].x + x[j].y * x[j].y + x[j].z * x[j].z + x[j].w * x[j].w;
        }
        s += __shfl_xor_sync(0xffffffffu, s, 1);
        s += __shfl_xor_sync(0xffffffffu, s, 2);
        ss += __shfl_xor_sync(0xffffffffu, ss, 1);
        ss += __shfl_xor_sync(0xffffffffu, ss, 2);
        float m = s * (1.f / 128.f);
        float var = ss * (1.f / 128.f) - m * m;
        float inv = rsqrtf(var + 1e-5f);
#pragma unroll
        for (int j = 0; j < 8; j++) {
            int col = seg * 32 + j * 4;
            float4 g = *(const float4*)(lng + col);
            float4 bb = *(const float4*)(lnb + col);
            float4 y;
            y.x = tf32r((x[j].x - m) * inv * g.x + bb.x);
            y.y = tf32r((x[j].y - m) * inv * g.y + bb.y);
            y.z = tf32r((x[j].z - m) * inv * g.z + bb.z);
            y.w = tf32r((x[j].w - m) * inv * g.w + bb.w);
            *(float4*)&As[row * 132 + col] = y;
        }
    } else {
#pragma unroll
        for (int j = 0; j < 8; j++) {
            int idx = t + j * 256;
            int r = idx >> 5;
            int c4 = (idx & 31) * 4;
            float4 v = *(const float4*)(Asrc + r * CZ + c4);
            v.x = tf32r(v.x); v.y = tf32r(v.y); v.z = tf32r(v.z); v.w = tf32r(v.w);
            *(float4*)&As[r * 132 + c4] = v;
        }
    }
#pragma unroll
    for (int j = 0; j < 16; j++) {
        int idx = t + j * 256;
        int r = idx >> 5;
        int c4 = (idx & 31) * 4;
        float4 v = *(const float4*)(W + (size_t)r * wstride + c4);
        v.x = tf32r(v.x); v.y = tf32r(v.y); v.z = tf32r(v.z); v.w = tf32r(v.w);
        *(float4*)&Bs[r * 132 + c4] = v;
    }
    __syncthreads();

    int warp = t >> 5, lane = t & 31;
    int g = lane >> 2, tid = lane & 3;
    int wm = warp >> 2, wn = warp & 3;

    float c[2][4][4];
#pragma unroll
    for (int mf = 0; mf < 2; mf++)
#pragma unroll
        for (int nf = 0; nf < 4; nf++)
#pragma unroll
            for (int i = 0; i < 4; i++) c[mf][nf][i] = 0.f;

    const unsigned* Au = (const unsigned*)As;
    const unsigned* Bu = (const unsigned*)Bs;

#pragma unroll
    for (int s = 0; s < 16; s++) {
        int k0 = s * 8;
        unsigned a[2][4];
#pragma unroll
        for (int mf = 0; mf < 2; mf++) {
            int rb = (wm * 32 + mf * 16 + g) * 132 + k0 + tid;
            a[mf][0] = Au[rb];
            a[mf][1] = Au[rb + 8 * 132];
            a[mf][2] = Au[rb + 4];
            a[mf][3] = Au[rb + 8 * 132 + 4];
        }
        unsigned b[4][2];
#pragma unroll
        for (int nf = 0; nf < 4; nf++) {
            int rb = (k0 + tid) * 132 + wn * 32 + nf * 8 + g;
            b[nf][0] = Bu[rb];
            b[nf][1] = Bu[rb + 4 * 132];
        }
#pragma unroll
        for (int mf = 0; mf < 2; mf++)
#pragma unroll
            for (int nf = 0; nf < 4; nf++)
                asm volatile(
                    "mma.sync.aligned.m16n8k8.row.col.f32.tf32.tf32.f32 "
                    "{%0,%1,%2,%3}, {%4,%5,%6,%7}, {%8,%9}, {%0,%1,%2,%3};"
                    : "+f"(c[mf][nf][0]), "+f"(c[mf][nf][1]),
                      "+f"(c[mf][nf][2]), "+f"(c[mf][nf][3])
                    : "r"(a[mf][0]), "r"(a[mf][1]), "r"(a[mf][2]), "r"(a[mf][3]),
                      "r"(b[nf][0]), "r"(b[nf][1]));
    }

#pragma unroll
    for (int nf = 0; nf < 4; nf++) {
        int col = wn * 32 + nf * 8 + tid * 2;
        float2 bi = *(const float2*)(bias + col);
#pragma unroll
        for (int mf = 0; mf < 2; mf++) {
            int row0 = eb * 64 + wm * 32 + mf * 16 + g;
            float x0 = c[mf][nf][0] + bi.x, x1 = c[mf][nf][1] + bi.y;
            float x2 = c[mf][nf][2] + bi.x, x3 = c[mf][nf][3] + bi.y;
            if (SIG) {
                x0 = 1.f / (1.f + __expf(-x0));
                x1 = 1.f / (1.f + __expf(-x1));
                x2 = 1.f / (1.f + __expf(-x2));
                x3 = 1.f / (1.f + __expf(-x3));
            }
            *(float2*)(dst + (size_t)row0 * CZ + col) = make_float2(x0, x1);
            *(float2*)(dst + (size_t)(row0 + 8) * CZ + col) = make_float2(x2, x3);
        }
    }
}

// ---------------- K2: q/k/v/og projections (LN fused) ---------------------------
__global__ __launch_bounds__(256) void k_proj_mma(
    const float* __restrict__ ef,
    const float* __restrict__ lng, const float* __restrict__ lnb,
    const float* __restrict__ Wq, const float* __restrict__ bq,
    const float* __restrict__ Wkv, const float* __restrict__ bkv,
    const float* __restrict__ Wog, const float* __restrict__ bog) {
    int y = blockIdx.y;
    if (y == 0)      mma_tile<false, true>(ef, lng, lnb, Wq, 128, bq, d_q, blockIdx.x);
    else if (y == 1) mma_tile<false, true>(ef, lng, lnb, Wkv, 256, bkv, d_k, blockIdx.x);
    else if (y == 2) mma_tile<false, true>(ef, lng, lnb, Wkv + 128, 256, bkv + 128, d_v, blockIdx.x);
    else             mma_tile<true, true>(ef, lng, lnb, Wog, 128, bog, d_og, blockIdx.x);
}

// ---------------- K5: output projection ------------------------------------------
__global__ __launch_bounds__(256) void k_out_mma(
    const float* __restrict__ Wout, const float* __restrict__ bout,
    float* __restrict__ out) {
    mma_tile<false, false>(d_gupd, nullptr, nullptr, Wout, 128, bout, out, blockIdx.x);
}

// ---------------- K3: per-pair bias + attention logits (loads hoisted) ------------
__global__ __launch_bounds__(256) void k_pair(
    const float* __restrict__ trans,
    const float* __restrict__ Wbg, const float* __restrict__ bbg,
    const float* __restrict__ Wtb) {
    __shared__ float s_B[CG][CZ];
    __shared__ float s_nr[CG];
    int n2 = blockIdx.x, t = threadIdx.x;
    if (t < CG) s_nr[t] = d_nr[n2 * CG + t];
    __syncthreads();
    {
        int c = t & 127, half = t >> 7;
#pragma unroll
        for (int i = half * 8; i < half * 8 + 8; i++) {
            float a = 0.f;
#pragma unroll
            for (int j = 0; j < CG; j++) a += s_nr[j] * Wbg[(i * CG + j) * CZ + c];
            s_B[i][c] = a;
        }
    }
    __syncthreads();

    int warp = t >> 5, lane = t & 31;
    int c0 = lane * 4;
    int hb = lane >> 3;
    ull bbg0 = *(const ull*)(bbg + c0);
    ull bbg1 = *(const ull*)(bbg + c0 + 2);
    float4 wtb0 = *(const float4*)(Wtb + (c0 + 0) * NH);
    float4 wtb1 = *(const float4*)(Wtb + (c0 + 1) * NH);
    float4 wtb2 = *(const float4*)(Wtb + (c0 + 2) * NH);
    float4 wtb3 = *(const float4*)(Wtb + (c0 + 3) * NH);
    float trx = trans[n2 * 3], try_ = trans[n2 * 3 + 1], trz = trans[n2 * 3 + 2];
    int beg = n2 * CAP2, end = beg + d_cnt2[n2];
    const float SCALE = 0.088388347648318447f;

    for (int m0 = beg + warp * 4; m0 < end; m0 += 32) {
        int np = end - m0; np = np > 4 ? 4 : np;
        int e0a[4], e1a[4], n1a[4], sla[4];
#pragma unroll
        for (int p = 0; p < 4; p++) {
            if (p < np) {
                int4 r = d_rec[m0 + p];
                e0a[p] = r.x; e1a[p] = r.y; n1a[p] = r.z; sla[p] = r.w;
            } else { e0a[p] = 0; e1a[p] = 0; n1a[p] = 0; sla[p] = 0; }
        }
        float nlv01 = d_nl[n1a[lane >> 4] * CG + (lane & 15)];
        float nlv23 = d_nl[n1a[2 + (lane >> 4)] * CG + (lane & 15)];

        float frme = 0.f;
        int i0me = 0;
        if (lane < 4) {
            int n1 = n1a[lane];
            float dx = trans[n1 * 3] - trx + 1e-8f;
            float dy = trans[n1 * 3 + 1] - try_ + 1e-8f;
            float dz = trans[n1 * 3 + 2] - trz + 1e-8f;
            float u = sqrtf(dx * dx + dy * dy + dz * dz) * LUT_SCALE;
            int i0 = (int)u;
            i0 = i0 > (LUT_N - 2) ? (LUT_N - 2) : i0;
            frme = u - (float)i0;
            i0me = i0;
        }

        // HOISTED: all LUT and q/k gathers issued before the gate loop so the
        // 16-step shuffle chain hides their latency.
        float db[4][4], qk[4];
#pragma unroll
        for (int p = 0; p < 4; p++) {
            float fr = __shfl_sync(0xffffffffu, frme, p);
            int i0 = __shfl_sync(0xffffffffu, i0me, p);
            float4 l0 = *(const float4*)(d_lut + (size_t)i0 * CZ + c0);
            float4 l1 = *(const float4*)(d_lut + (size_t)(i0 + 1) * CZ + c0);
            db[p][0] = l0.x + fr * (l1.x - l0.x);
            db[p][1] = l0.y + fr * (l1.y - l0.y);
            db[p][2] = l0.z + fr * (l1.z - l0.z);
            db[p][3] = l0.w + fr * (l1.w - l0.w);
            float4 q4 = *(const float4*)(d_q + (size_t)e1a[p] * CZ + c0);
            float4 k4 = *(const float4*)(d_k + (size_t)e0a[p] * CZ + c0);
            qk[p] = (q4.x * k4.x + q4.y * k4.y + q4.z * k4.z + q4.w * k4.w) * SCALE;
        }

        ull g0[4], g1[4];
#pragma unroll
        for (int p = 0; p < 4; p++) { g0[p] = bbg0; g1[p] = bbg1; }
#pragma unroll
        for (int i = 0; i < CG; i++) {
            ull b0 = *(const ull*)&s_B[i][c0];
            ull b1 = *(const ull*)&s_B[i][c0 + 2];
#pragma unroll
            for (int p = 0; p < 4; p++) {
                float nli = __shfl_sync(0xffffffffu, (p < 2) ? nlv01 : nlv23,
                                        ((p & 1) << 4) | i);
                ull nd = pkdup(nli);
                g0[p] = ffma2(nd, b0, g0[p]);
                g1[p] = ffma2(nd, b1, g1[p]);
            }
        }

#pragma unroll
        for (int p = 0; p < 4; p++) {
            if (p >= np) break;
            float ga, gb, gc, gd;
            upk2(g0[p], ga, gb);
            upk2(g1[p], gc, gd);
            float tv0 = db[p][0] * sigmoid_fast(ga);
            float tv1 = db[p][1] * sigmoid_fast(gb);
            float tv2 = db[p][2] * sigmoid_fast(gc);
            float tv3 = db[p][3] * sigmoid_fast(gd);

            float v0 = tv0 * wtb0.x + tv1 * wtb1.x + tv2 * wtb2.x + tv3 * wtb3.x;
            float v1 = tv0 * wtb0.y + tv1 * wtb1.y + tv2 * wtb2.y + tv3 * wtb3.y;
            float v2 = tv0 * wtb0.z + tv1 * wtb1.z + tv2 * wtb2.z + tv3 * wtb3.z;
            float v3 = tv0 * wtb0.w + tv1 * wtb1.w + tv2 * wtb2.w + tv3 * wtb3.w;
            v0 += (hb == 0) ? qk[p] : 0.f;
            v1 += (hb == 1) ? qk[p] : 0.f;
            v2 += (hb == 2) ? qk[p] : 0.f;
            v3 += (hb == 3) ? qk[p] : 0.f;
#pragma unroll
            for (int o = 16; o > 0; o >>= 1) {
                v0 += __shfl_xor_sync(0xffffffffu, v0, o);
                v1 += __shfl_xor_sync(0xffffffffu, v1, o);
                v2 += __shfl_xor_sync(0xffffffffu, v2, o);
                v3 += __shfl_xor_sync(0xffffffffu, v3, o);
            }
            if (lane == 0)
                *(float4*)&d_attn[(size_t)sla[p] * 4] = make_float4(
                    __expf(v0), __expf(v1), __expf(v2), __expf(v3));
        }
    }
}

// ---------------- K4: segment softmax (pre-exp'd) + V agg + out gate ---------------
__global__ __launch_bounds__(256) void k_soft() {
    int warp = threadIdx.x >> 5, lane = threadIdx.x & 31;
    int tgt = blockIdx.x * 8 + warp;
    if (tgt >= E_EDGES) return;
    int beg = tgt * CAP1, end = beg + d_cnt[tgt];
    int hb = lane >> 3;
    int c0 = lane * 4;

    float sum = 0.f;
    float ax = 0.f, ay = 0.f, az = 0.f, aw = 0.f;
    float a_n = 0.f;
    int s_n = 0;
    if (beg < end) { a_n = d_attn[(size_t)beg * 4 + hb]; s_n = d_src[beg]; }
    for (int m = beg; m < end; m++) {
        float pp = a_n;
        int s = s_n;
        if (m + 1 < end) { a_n = d_attn[(size_t)(m + 1) * 4 + hb]; s_n = d_src[m + 1]; }
        sum += pp;
        float4 v = *(const float4*)(d_v + (size_t)s * CZ + c0);
        ax += pp * v.x; ay += pp * v.y; az += pp * v.z; aw += pp * v.w;
    }
    float inv = 1.f / (sum + 1e-16f);
    float4 og = *(const float4*)(d_og + (size_t)tgt * CZ + c0);
    float4 r = make_float4(ax * inv * og.x, ay * inv * og.y,
                           az * inv * og.z, aw * inv * og.w);
    *(float4*)(d_gupd + (size_t)tgt * CZ + c0) = r;
}

// ---------------- launch ------------------------------------------------------------
extern "C" void kernel_launch(void* const* d_in, const int* in_sizes, int n_in,
                              void* d_out, int out_size) {
    const float* node_features = (const float*)d_in[0];
    const float* node_trans    = (const float*)d_in[1];
    const float* edge_features = (const float*)d_in[2];
    const int*   edge_index    = (const int*)d_in[3];
    const int*   ee_index      = (const int*)d_in[4];
    const float* ln_g  = (const float*)d_in[5];
    const float* ln_b  = (const float*)d_in[6];
    const float* W_nl  = (const float*)d_in[7];
    const float* b_nl  = (const float*)d_in[8];
    const float* W_nr  = (const float*)d_in[9];
    const float* b_nr  = (const float*)d_in[10];
    const float* W_bg  = (const float*)d_in[11];
    const float* b_bg  = (const float*)d_in[12];
    const float* W_db  = (const float*)d_in[13];
    const float* b_db  = (const float*)d_in[14];
    const float* W_tb  = (const float*)d_in[15];
    const float* W_q   = (const float*)d_in[16];
    const float* b_q   = (const float*)d_in[17];
    const float* W_kv  = (const float*)d_in[18];
    const float* b_kv  = (const float*)d_in[19];
    const float* W_og  = (const float*)d_in[20];
    const float* b_og  = (const float*)d_in[21];
    const float* W_out = (const float*)d_in[22];
    const float* b_out = (const float*)d_in[23];
    float* out = (float*)d_out;

    cudaFuncSetAttribute(k_proj_mma, cudaFuncAttributeMaxDynamicSharedMemorySize, MMA_SMEM);
    cudaFuncSetAttribute(k_out_mma, cudaFuncAttributeMaxDynamicSharedMemorySize, MMA_SMEM);

    k_init<<<64, 512>>>();                                                   // 0
    k_misc<<<2176, 256>>>(node_features, W_nl, b_nl, W_nr, b_nr,             // 1
                          edge_index, ee_index, W_db, b_db);
    k_proj_mma<<<dim3(E_EDGES / 64, 4), 256, MMA_SMEM>>>(                    // 2
        edge_features, ln_g, ln_b, W_q, b_q, W_kv, b_kv, W_og, b_og);
    k_pair<<<N_NODES, 256>>>(node_trans, W_bg, b_bg, W_tb);                  // 3 (ncu slot)
    k_soft<<<E_EDGES / 8, 256>>>();                                          // 4
    k_out_mma<<<E_EDGES / 64, 256, MMA_SMEM>>>(W_out, b_out, out);           // 5
}

// round 9
// speedup vs baseline: 1.0611x; 1.0611x over previous
#include <cuda_runtime.h>
#include <math.h>

typedef unsigned long long ull;

#define N_NODES 1024
#define E_EDGES 32768
#define EE_PAIRS 262144
#define CS 384
#define CZ 128
#define CG 16
#define NH 4
#define NR 64
#define LUT_N 8192
#define LUT_SCALE 256.0f
#define CAP1 64
#define CAP2 768

#define MMA_SMEM ((64 + 128) * 132 * 4)

// ---------------- scratch ---------------------------------------------------
__device__ float d_ef[E_EDGES * CZ];
__device__ float d_nl[N_NODES * CG];
__device__ float d_nr[N_NODES * CG];
__device__ float d_q[E_EDGES * CZ];
__device__ float d_k[E_EDGES * CZ];
__device__ float d_v[E_EDGES * CZ];
__device__ float d_og[E_EDGES * CZ];
__device__ float d_attn[(size_t)E_EDGES * CAP1 * NH];
__device__ float d_gupd[E_EDGES * CZ];
__device__ float d_lut[LUT_N * CZ];
__device__ int   d_cnt[E_EDGES];
__device__ int   d_cnt2[N_NODES];
__device__ int   d_src[E_EDGES * CAP1];
__device__ int4  d_rec[N_NODES * CAP2];

// ---------------- helpers ----------------------------------------------------
__device__ __forceinline__ ull pk2(float lo, float hi) {
    ull r;
    asm("mov.b64 %0, {%1, %2};" : "=l"(r) : "f"(lo), "f"(hi));
    return r;
}
__device__ __forceinline__ ull pkdup(float v) { return pk2(v, v); }
__device__ __forceinline__ void upk2(ull p, float& lo, float& hi) {
    asm("mov.b64 {%0, %1}, %2;" : "=f"(lo), "=f"(hi) : "l"(p));
}
__device__ __forceinline__ ull ffma2(ull a, ull b, ull c) {
    ull d;
    asm("fma.rn.f32x2 %0, %1, %2, %3;" : "=l"(d) : "l"(a), "l"(b), "l"(c));
    return d;
}
__device__ __forceinline__ float tf32r(float f) {
    unsigned u;
    asm("cvt.rna.tf32.f32 %0, %1;" : "=r"(u) : "f"(f));
    return __uint_as_float(u);
}
__device__ __forceinline__ float sigmoid_fast(float x) {
    float x2 = x * x;
    float s = 0.5f + x * (0.25f + x2 * (-2.0833334e-2f + x2 * 2.0833334e-3f));
    if (fabsf(x) > 0.7f) s = 1.f / (1.f + __expf(-x));
    return s;
}

// ---------------- K0: zero counters -------------------------------------------
__global__ void k_init() {
    int i = blockIdx.x * blockDim.x + threadIdx.x;
    for (; i < E_EDGES; i += gridDim.x * blockDim.x) {
        d_cnt[i] = 0;
        if (i < N_NODES) d_cnt2[i] = 0;
    }
}

// ---------------- K1: fused nlr + bucket-build + lut + layernorm ---------------
// blocks [0,1024): nlr  [1024,2048): build  [2048,2176): lut  [2176,3200): LN
__global__ __launch_bounds__(256) void k_misc(
    const float* __restrict__ nf,
    const float* __restrict__ Wnl, const float* __restrict__ bnl,
    const float* __restrict__ Wnr, const float* __restrict__ bnr,
    const int* __restrict__ eidx, const int* __restrict__ eeidx,
    const float* __restrict__ Wdb, const float* __restrict__ bdb,
    const float* __restrict__ ef,
    const float* __restrict__ lng, const float* __restrict__ lnb) {
    int b = blockIdx.x, t = threadIdx.x;
    if (b < 1024) {
        __shared__ float s_nf[CS];
        int n = b;
        for (int i = t; i < CS; i += 256) s_nf[i] = nf[n * CS + i];
        __syncthreads();
        if (t < CG) {
            float a = bnl[t];
            for (int k = 0; k < CS; k++) a += s_nf[k] * Wnl[k * CG + t];
            d_nl[n * CG + t] = a;
        } else if (t < 2 * CG) {
            int c = t - CG;
            float a = bnr[c];
            for (int k = 0; k < CS; k++) a += s_nf[k] * Wnr[k * CG + c];
            d_nr[n * CG + c] = a;
        }
    } else if (b < 2048) {
        int ee = (b - 1024) * 256 + t;
        int e0 = eeidx[ee];
        int e1 = eeidx[EE_PAIRS + ee];
        int p = atomicAdd(&d_cnt[e1], 1);
        p = p < CAP1 ? p : CAP1 - 1;
        int slot = e1 * CAP1 + p;
        d_src[slot] = e0;
        int n2 = eidx[e0];
        int n1 = eidx[e1];
        int p2 = atomicAdd(&d_cnt2[n2], 1);
        p2 = p2 < CAP2 ? p2 : CAP2 - 1;
        d_rec[n2 * CAP2 + p2] = make_int4(e0, e1, n1, slot);
    } else if (b < 2176) {
        __shared__ float s_w[NR][CZ];
        __shared__ float s_rbf[2][NR];
        int blk = b - 2048;
        int c = t & 127, half = t >> 7;
        for (int i = t; i < NR * CZ; i += 256) ((float*)s_w)[i] = Wdb[i];
        float bd = bdb[c];
        __syncthreads();
        const float MU_STEP = 20.f / 63.f;
        const float SIG_INV = 3.2f;
        for (int row = 0; row < 64; row += 2) {
            int dI = blk * 64 + row + half;
            float dist = (float)dI * (1.0f / LUT_SCALE);
            if (c < NR) {
                float tt = (dist - (float)c * MU_STEP) * SIG_INV;
                s_rbf[half][c] = __expf(-tt * tt);
            }
            __syncthreads();
            float a = bd;
#pragma unroll 16
            for (int r = 0; r < NR; r++) a += s_rbf[half][r] * s_w[r][c];
            d_lut[dI * CZ + c] = a;
            __syncthreads();
        }
    } else {
        // layernorm: 32 edges per block
        int warp = t >> 5, lane = t & 31;
        int e0 = (b - 2176) * 32;
#pragma unroll
        for (int r = 0; r < 4; r++) {
            int ge = e0 + warp * 4 + r;
            float4 x = ((const float4*)(ef + (size_t)ge * CZ))[lane];
            float s = x.x + x.y + x.z + x.w;
            float ss = x.x * x.x + x.y * x.y + x.z * x.z + x.w * x.w;
#pragma unroll
            for (int o = 16; o > 0; o >>= 1) {
                s += __shfl_xor_sync(0xffffffffu, s, o);
                ss += __shfl_xor_sync(0xffffffffu, ss, o);
            }
            float m = s * (1.f / 128.f);
            float var = ss * (1.f / 128.f) - m * m;
            float inv = rsqrtf(var + 1e-5f);
            float4 g = ((const float4*)lng)[lane];
            float4 bb = ((const float4*)lnb)[lane];
            float4 y;
            y.x = (x.x - m) * inv * g.x + bb.x;
            y.y = (x.y - m) * inv * g.y + bb.y;
            y.z = (x.z - m) * inv * g.z + bb.z;
            y.w = (x.w - m) * inv * g.w + bb.w;
            ((float4*)(d_ef + (size_t)ge * CZ))[lane] = y;
        }
    }
}

// ---------------- generic 64x128 tf32 MMA tile -----------------------------------
template <bool SIG>
__device__ __forceinline__ void mma_tile(
    const float* __restrict__ Ag, const float* __restrict__ W, int wstride,
    const float* __restrict__ bias, float* __restrict__ dst, int eb) {
    extern __shared__ float sm[];
    float* As = sm;
    float* Bs = sm + 64 * 132;
    int t = threadIdx.x;

    const float* Asrc = Ag + (size_t)eb * 64 * CZ;
#pragma unroll
    for (int j = 0; j < 8; j++) {
        int idx = t + j * 256;
        int r = idx >> 5;
        int c4 = (idx & 31) * 4;
        float4 v = *(const float4*)(Asrc + r * CZ + c4);
        v.x = tf32r(v.x); v.y = tf32r(v.y); v.z = tf32r(v.z); v.w = tf32r(v.w);
        *(float4*)&As[r * 132 + c4] = v;
    }
#pragma unroll
    for (int j = 0; j < 16; j++) {
        int idx = t + j * 256;
        int r = idx >> 5;
        int c4 = (idx & 31) * 4;
        float4 v = *(const float4*)(W + (size_t)r * wstride + c4);
        v.x = tf32r(v.x); v.y = tf32r(v.y); v.z = tf32r(v.z); v.w = tf32r(v.w);
        *(float4*)&Bs[r * 132 + c4] = v;
    }
    __syncthreads();

    int warp = t >> 5, lane = t & 31;
    int g = lane >> 2, tid = lane & 3;
    int wm = warp >> 2, wn = warp & 3;

    float c[2][4][4];
#pragma unroll
    for (int mf = 0; mf < 2; mf++)
#pragma unroll
        for (int nf = 0; nf < 4; nf++)
#pragma unroll
            for (int i = 0; i < 4; i++) c[mf][nf][i] = 0.f;

    const unsigned* Au = (const unsigned*)As;
    const unsigned* Bu = (const unsigned*)Bs;

#pragma unroll
    for (int s = 0; s < 16; s++) {
        int k0 = s * 8;
        unsigned a[2][4];
#pragma unroll
        for (int mf = 0; mf < 2; mf++) {
            int rb = (wm * 32 + mf * 16 + g) * 132 + k0 + tid;
            a[mf][0] = Au[rb];
            a[mf][1] = Au[rb + 8 * 132];
            a[mf][2] = Au[rb + 4];
            a[mf][3] = Au[rb + 8 * 132 + 4];
        }
        unsigned b[4][2];
#pragma unroll
        for (int nf = 0; nf < 4; nf++) {
            int rb = (k0 + tid) * 132 + wn * 32 + nf * 8 + g;
            b[nf][0] = Bu[rb];
            b[nf][1] = Bu[rb + 4 * 132];
        }
#pragma unroll
        for (int mf = 0; mf < 2; mf++)
#pragma unroll
            for (int nf = 0; nf < 4; nf++)
                asm volatile(
                    "mma.sync.aligned.m16n8k8.row.col.f32.tf32.tf32.f32 "
                    "{%0,%1,%2,%3}, {%4,%5,%6,%7}, {%8,%9}, {%0,%1,%2,%3};"
                    : "+f"(c[mf][nf][0]), "+f"(c[mf][nf][1]),
                      "+f"(c[mf][nf][2]), "+f"(c[mf][nf][3])
                    : "r"(a[mf][0]), "r"(a[mf][1]), "r"(a[mf][2]), "r"(a[mf][3]),
                      "r"(b[nf][0]), "r"(b[nf][1]));
    }

#pragma unroll
    for (int nf = 0; nf < 4; nf++) {
        int col = wn * 32 + nf * 8 + tid * 2;
        float2 bi = *(const float2*)(bias + col);
#pragma unroll
        for (int mf = 0; mf < 2; mf++) {
            int row0 = eb * 64 + wm * 32 + mf * 16 + g;
            float x0 = c[mf][nf][0] + bi.x, x1 = c[mf][nf][1] + bi.y;
            float x2 = c[mf][nf][2] + bi.x, x3 = c[mf][nf][3] + bi.y;
            if (SIG) {
                x0 = 1.f / (1.f + __expf(-x0));
                x1 = 1.f / (1.f + __expf(-x1));
                x2 = 1.f / (1.f + __expf(-x2));
                x3 = 1.f / (1.f + __expf(-x3));
            }
            *(float2*)(dst + (size_t)row0 * CZ + col) = make_float2(x0, x1);
            *(float2*)(dst + (size_t)(row0 + 8) * CZ + col) = make_float2(x2, x3);
        }
    }
}

// ---------------- K2: q/k/v/og projections ---------------------------------------
__global__ __launch_bounds__(256) void k_proj_mma(
    const float* __restrict__ Wq, const float* __restrict__ bq,
    const float* __restrict__ Wkv, const float* __restrict__ bkv,
    const float* __restrict__ Wog, const float* __restrict__ bog) {
    int y = blockIdx.y;
    if (y == 0)      mma_tile<false>(d_ef, Wq, 128, bq, d_q, blockIdx.x);
    else if (y == 1) mma_tile<false>(d_ef, Wkv, 256, bkv, d_k, blockIdx.x);
    else if (y == 2) mma_tile<false>(d_ef, Wkv + 128, 256, bkv + 128, d_v, blockIdx.x);
    else             mma_tile<true>(d_ef, Wog, 128, bog, d_og, blockIdx.x);
}

// ---------------- K5: output projection -------------------------------------------
__global__ __launch_bounds__(256) void k_out_mma(
    const float* __restrict__ Wout, const float* __restrict__ bout,
    float* __restrict__ out) {
    mma_tile<false>(d_gupd, Wout, 128, bout, out, blockIdx.x);
}

// ---------------- K3: per-pair bias + attention logits -----------------------------
// __launch_bounds__(256,3): 3 blocks/SM for latency hiding (A/B vs round 8's 2).
__global__ __launch_bounds__(256, 3) void k_pair(
    const float* __restrict__ trans,
    const float* __restrict__ Wbg, const float* __restrict__ bbg,
    const float* __restrict__ Wtb) {
    __shared__ float s_B[CG][CZ];
    __shared__ float s_nr[CG];
    int n2 = blockIdx.x, t = threadIdx.x;
    if (t < CG) s_nr[t] = d_nr[n2 * CG + t];
    __syncthreads();
    {
        int c = t & 127, half = t >> 7;
#pragma unroll
        for (int i = half * 8; i < half * 8 + 8; i++) {
            float a = 0.f;
#pragma unroll
            for (int j = 0; j < CG; j++) a += s_nr[j] * Wbg[(i * CG + j) * CZ + c];
            s_B[i][c] = a;
        }
    }
    __syncthreads();

    int warp = t >> 5, lane = t & 31;
    int c0 = lane * 4;
    int hb = lane >> 3;
    ull bbg0 = *(const ull*)(bbg + c0);
    ull bbg1 = *(const ull*)(bbg + c0 + 2);
    float4 wtb0 = *(const float4*)(Wtb + (c0 + 0) * NH);
    float4 wtb1 = *(const float4*)(Wtb + (c0 + 1) * NH);
    float4 wtb2 = *(const float4*)(Wtb + (c0 + 2) * NH);
    float4 wtb3 = *(const float4*)(Wtb + (c0 + 3) * NH);
    float trx = trans[n2 * 3], try_ = trans[n2 * 3 + 1], trz = trans[n2 * 3 + 2];
    int beg = n2 * CAP2, end = beg + d_cnt2[n2];
    const float SCALE = 0.088388347648318447f;

    for (int m0 = beg + warp * 4; m0 < end; m0 += 32) {
        int np = end - m0; np = np > 4 ? 4 : np;
        int e0a[4], e1a[4], n1a[4], sla[4];
#pragma unroll
        for (int p = 0; p < 4; p++) {
            if (p < np) {
                int4 r = d_rec[m0 + p];
                e0a[p] = r.x; e1a[p] = r.y; n1a[p] = r.z; sla[p] = r.w;
            } else { e0a[p] = 0; e1a[p] = 0; n1a[p] = 0; sla[p] = 0; }
        }
        float nlv01 = d_nl[n1a[lane >> 4] * CG + (lane & 15)];
        float nlv23 = d_nl[n1a[2 + (lane >> 4)] * CG + (lane & 15)];

        float frme = 0.f;
        int i0me = 0;
        if (lane < 4) {
            int n1 = n1a[lane];
            float dx = trans[n1 * 3] - trx + 1e-8f;
            float dy = trans[n1 * 3 + 1] - try_ + 1e-8f;
            float dz = trans[n1 * 3 + 2] - trz + 1e-8f;
            float u = sqrtf(dx * dx + dy * dy + dz * dz) * LUT_SCALE;
            int i0 = (int)u;
            i0 = i0 > (LUT_N - 2) ? (LUT_N - 2) : i0;
            frme = u - (float)i0;
            i0me = i0;
        }

        float db[4][4], qk[4];
#pragma unroll
        for (int p = 0; p < 4; p++) {
            float fr = __shfl_sync(0xffffffffu, frme, p);
            int i0 = __shfl_sync(0xffffffffu, i0me, p);
            float4 l0 = *(const float4*)(d_lut + (size_t)i0 * CZ + c0);
            float4 l1 = *(const float4*)(d_lut + (size_t)(i0 + 1) * CZ + c0);
            db[p][0] = l0.x + fr * (l1.x - l0.x);
            db[p][1] = l0.y + fr * (l1.y - l0.y);
            db[p][2] = l0.z + fr * (l1.z - l0.z);
            db[p][3] = l0.w + fr * (l1.w - l0.w);
            float4 q4 = *(const float4*)(d_q + (size_t)e1a[p] * CZ + c0);
            float4 k4 = *(const float4*)(d_k + (size_t)e0a[p] * CZ + c0);
            qk[p] = (q4.x * k4.x + q4.y * k4.y + q4.z * k4.z + q4.w * k4.w) * SCALE;
        }

        ull g0[4], g1[4];
#pragma unroll
        for (int p = 0; p < 4; p++) { g0[p] = bbg0; g1[p] = bbg1; }
#pragma unroll
        for (int i = 0; i < CG; i++) {
            ull b0 = *(const ull*)&s_B[i][c0];
            ull b1 = *(const ull*)&s_B[i][c0 + 2];
#pragma unroll
            for (int p = 0; p < 4; p++) {
                float nli = __shfl_sync(0xffffffffu, (p < 2) ? nlv01 : nlv23,
                                        ((p & 1) << 4) | i);
                ull nd = pkdup(nli);
                g0[p] = ffma2(nd, b0, g0[p]);
                g1[p] = ffma2(nd, b1, g1[p]);
            }
        }

#pragma unroll
        for (int p = 0; p < 4; p++) {
            if (p >= np) break;
            float ga, gb, gc, gd;
            upk2(g0[p], ga, gb);
            upk2(g1[p], gc, gd);
            float tv0 = db[p][0] * sigmoid_fast(ga);
            float tv1 = db[p][1] * sigmoid_fast(gb);
            float tv2 = db[p][2] * sigmoid_fast(gc);
            float tv3 = db[p][3] * sigmoid_fast(gd);

            float v0 = tv0 * wtb0.x + tv1 * wtb1.x + tv2 * wtb2.x + tv3 * wtb3.x;
            float v1 = tv0 * wtb0.y + tv1 * wtb1.y + tv2 * wtb2.y + tv3 * wtb3.y;
            float v2 = tv0 * wtb0.z + tv1 * wtb1.z + tv2 * wtb2.z + tv3 * wtb3.z;
            float v3 = tv0 * wtb0.w + tv1 * wtb1.w + tv2 * wtb2.w + tv3 * wtb3.w;
            v0 += (hb == 0) ? qk[p] : 0.f;
            v1 += (hb == 1) ? qk[p] : 0.f;
            v2 += (hb == 2) ? qk[p] : 0.f;
            v3 += (hb == 3) ? qk[p] : 0.f;
#pragma unroll
            for (int o = 16; o > 0; o >>= 1) {
                v0 += __shfl_xor_sync(0xffffffffu, v0, o);
                v1 += __shfl_xor_sync(0xffffffffu, v1, o);
                v2 += __shfl_xor_sync(0xffffffffu, v2, o);
                v3 += __shfl_xor_sync(0xffffffffu, v3, o);
            }
            if (lane == 0)
                *(float4*)&d_attn[(size_t)sla[p] * 4] = make_float4(
                    __expf(v0), __expf(v1), __expf(v2), __expf(v3));
        }
    }
}

// ---------------- K4: segment softmax (pre-exp'd) + V agg + out gate ---------------
__global__ __launch_bounds__(256) void k_soft() {
    int warp = threadIdx.x >> 5, lane = threadIdx.x & 31;
    int tgt = blockIdx.x * 8 + warp;
    if (tgt >= E_EDGES) return;
    int beg = tgt * CAP1, end = beg + d_cnt[tgt];
    int hb = lane >> 3;
    int c0 = lane * 4;

    float sum = 0.f;
    float ax = 0.f, ay = 0.f, az = 0.f, aw = 0.f;
    float a_n = 0.f;
    int s_n = 0;
    if (beg < end) { a_n = d_attn[(size_t)beg * 4 + hb]; s_n = d_src[beg]; }
    for (int m = beg; m < end; m++) {
        float pp = a_n;
        int s = s_n;
        if (m + 1 < end) { a_n = d_attn[(size_t)(m + 1) * 4 + hb]; s_n = d_src[m + 1]; }
        sum += pp;
        float4 v = *(const float4*)(d_v + (size_t)s * CZ + c0);
        ax += pp * v.x; ay += pp * v.y; az += pp * v.z; aw += pp * v.w;
    }
    float inv = 1.f / (sum + 1e-16f);
    float4 og = *(const float4*)(d_og + (size_t)tgt * CZ + c0);
    float4 r = make_float4(ax * inv * og.x, ay * inv * og.y,
                           az * inv * og.z, aw * inv * og.w);
    *(float4*)(d_gupd + (size_t)tgt * CZ + c0) = r;
}

// ---------------- launch ------------------------------------------------------------
extern "C" void kernel_launch(void* const* d_in, const int* in_sizes, int n_in,
                              void* d_out, int out_size) {
    const float* node_features = (const float*)d_in[0];
    const float* node_trans    = (const float*)d_in[1];
    const float* edge_features = (const float*)d_in[2];
    const int*   edge_index    = (const int*)d_in[3];
    const int*   ee_index      = (const int*)d_in[4];
    const float* ln_g  = (const float*)d_in[5];
    const float* ln_b  = (const float*)d_in[6];
    const float* W_nl  = (const float*)d_in[7];
    const float* b_nl  = (const float*)d_in[8];
    const float* W_nr  = (const float*)d_in[9];
    const float* b_nr  = (const float*)d_in[10];
    const float* W_bg  = (const float*)d_in[11];
    const float* b_bg  = (const float*)d_in[12];
    const float* W_db  = (const float*)d_in[13];
    const float* b_db  = (const float*)d_in[14];
    const float* W_tb  = (const float*)d_in[15];
    const float* W_q   = (const float*)d_in[16];
    const float* b_q   = (const float*)d_in[17];
    const float* W_kv  = (const float*)d_in[18];
    const float* b_kv  = (const float*)d_in[19];
    const float* W_og  = (const float*)d_in[20];
    const float* b_og  = (const float*)d_in[21];
    const float* W_out = (const float*)d_in[22];
    const float* b_out = (const float*)d_in[23];
    float* out = (float*)d_out;

    cudaFuncSetAttribute(k_proj_mma, cudaFuncAttributeMaxDynamicSharedMemorySize, MMA_SMEM);
    cudaFuncSetAttribute(k_out_mma, cudaFuncAttributeMaxDynamicSharedMemorySize, MMA_SMEM);

    k_init<<<64, 512>>>();                                                   // 0
    k_misc<<<3200, 256>>>(node_features, W_nl, b_nl, W_nr, b_nr,             // 1
                          edge_index, ee_index, W_db, b_db,
                          edge_features, ln_g, ln_b);
    k_proj_mma<<<dim3(E_EDGES / 64, 4), 256, MMA_SMEM>>>(                    // 2
        W_q, b_q, W_kv, b_kv, W_og, b_og);
    k_pair<<<N_NODES, 256>>>(node_trans, W_bg, b_bg, W_tb);                  // 3 (ncu slot)
    k_soft<<<E_EDGES / 8, 256>>>();                                          // 4
    k_out_mma<<<E_EDGES / 64, 256, MMA_SMEM>>>(W_out, b_out, out);           // 5
}

// round 11
// speedup vs baseline: 1.1098x; 1.0459x over previous
#include <cuda_runtime.h>
#include <math.h>

typedef unsigned long long ull;

#define N_NODES 1024
#define E_EDGES 32768
#define EE_PAIRS 262144
#define CS 384
#define CZ 128
#define CG 16
#define NH 4
#define NR 64
#define LUT_N 8192
#define LUT_SCALE 256.0f
#define CAP1 64
#define CAP2 768

#define MMA_SMEM ((64 + 128) * 132 * 4)

// ---------------- scratch ---------------------------------------------------
__device__ float d_ef[E_EDGES * CZ];
__device__ float d_nl[N_NODES * CG];
__device__ float d_nr[N_NODES * CG];
__device__ float d_q[E_EDGES * CZ];
__device__ float d_k[E_EDGES * CZ];
__device__ float d_v[E_EDGES * CZ];
__device__ float d_og[E_EDGES * CZ];
__device__ float d_attn[(size_t)E_EDGES * CAP1 * NH];
__device__ float d_gupd[E_EDGES * CZ];
__device__ float d_lut[LUT_N * CZ];
__device__ int   d_cnt[E_EDGES];
__device__ int   d_cnt2[N_NODES];
__device__ int   d_src[E_EDGES * CAP1];
__device__ int4  d_rec[N_NODES * CAP2];

// ---------------- helpers ----------------------------------------------------
__device__ __forceinline__ ull pk2(float lo, float hi) {
    ull r;
    asm("mov.b64 %0, {%1, %2};" : "=l"(r) : "f"(lo), "f"(hi));
    return r;
}
__device__ __forceinline__ ull pkdup(float v) { return pk2(v, v); }
__device__ __forceinline__ void upk2(ull p, float& lo, float& hi) {
    asm("mov.b64 {%0, %1}, %2;" : "=f"(lo), "=f"(hi) : "l"(p));
}
__device__ __forceinline__ ull ffma2(ull a, ull b, ull c) {
    ull d;
    asm("fma.rn.f32x2 %0, %1, %2, %3;" : "=l"(d) : "l"(a), "l"(b), "l"(c));
    return d;
}
__device__ __forceinline__ float tf32r(float f) {
    unsigned u;
    asm("cvt.rna.tf32.f32 %0, %1;" : "=r"(u) : "f"(f));
    return __uint_as_float(u);
}
__device__ __forceinline__ float sigmoid_fast(float x) {
    float x2 = x * x;
    float s = 0.5f + x * (0.25f + x2 * (-2.0833334e-2f + x2 * 2.0833334e-3f));
    if (fabsf(x) > 0.7f) s = 1.f / (1.f + __expf(-x));
    return s;
}

// ---------------- K0: zero counters -------------------------------------------
__global__ void k_init() {
    int i = blockIdx.x * blockDim.x + threadIdx.x;
    for (; i < E_EDGES; i += gridDim.x * blockDim.x) {
        d_cnt[i] = 0;
        if (i < N_NODES) d_cnt2[i] = 0;
    }
}

// ---------------- K1: fused nlr + bucket-build + lut + layernorm ---------------
__global__ __launch_bounds__(256) void k_misc(
    const float* __restrict__ nf,
    const float* __restrict__ Wnl, const float* __restrict__ bnl,
    const float* __restrict__ Wnr, const float* __restrict__ bnr,
    const int* __restrict__ eidx, const int* __restrict__ eeidx,
    const float* __restrict__ Wdb, const float* __restrict__ bdb,
    const float* __restrict__ ef,
    const float* __restrict__ lng, const float* __restrict__ lnb) {
    int b = blockIdx.x, t = threadIdx.x;
    if (b < 1024) {
        __shared__ float s_nf[CS];
        int n = b;
        for (int i = t; i < CS; i += 256) s_nf[i] = nf[n * CS + i];
        __syncthreads();
        if (t < CG) {
            float a = bnl[t];
            for (int k = 0; k < CS; k++) a += s_nf[k] * Wnl[k * CG + t];
            d_nl[n * CG + t] = a;
        } else if (t < 2 * CG) {
            int c = t - CG;
            float a = bnr[c];
            for (int k = 0; k < CS; k++) a += s_nf[k] * Wnr[k * CG + c];
            d_nr[n * CG + c] = a;
        }
    } else if (b < 2048) {
        int ee = (b - 1024) * 256 + t;
        int e0 = eeidx[ee];
        int e1 = eeidx[EE_PAIRS + ee];
        int p = atomicAdd(&d_cnt[e1], 1);
        p = p < CAP1 ? p : CAP1 - 1;
        int slot = e1 * CAP1 + p;
        d_src[slot] = e0;
        int n2 = eidx[e0];
        int n1 = eidx[e1];
        int p2 = atomicAdd(&d_cnt2[n2], 1);
        p2 = p2 < CAP2 ? p2 : CAP2 - 1;
        d_rec[n2 * CAP2 + p2] = make_int4(e0, e1, n1, slot);
    } else if (b < 2176) {
        __shared__ float s_w[NR][CZ];
        __shared__ float s_rbf[2][NR];
        int blk = b - 2048;
        int c = t & 127, half = t >> 7;
        for (int i = t; i < NR * CZ; i += 256) ((float*)s_w)[i] = Wdb[i];
        float bd = bdb[c];
        __syncthreads();
        const float MU_STEP = 20.f / 63.f;
        const float SIG_INV = 3.2f;
        for (int row = 0; row < 64; row += 2) {
            int dI = blk * 64 + row + half;
            float dist = (float)dI * (1.0f / LUT_SCALE);
            if (c < NR) {
                float tt = (dist - (float)c * MU_STEP) * SIG_INV;
                s_rbf[half][c] = __expf(-tt * tt);
            }
            __syncthreads();
            float a = bd;
#pragma unroll 16
            for (int r = 0; r < NR; r++) a += s_rbf[half][r] * s_w[r][c];
            d_lut[dI * CZ + c] = a;
            __syncthreads();
        }
    } else {
        int warp = t >> 5, lane = t & 31;
        int e0 = (b - 2176) * 32;
#pragma unroll
        for (int r = 0; r < 4; r++) {
            int ge = e0 + warp * 4 + r;
            float4 x = ((const float4*)(ef + (size_t)ge * CZ))[lane];
            float s = x.x + x.y + x.z + x.w;
            float ss = x.x * x.x + x.y * x.y + x.z * x.z + x.w * x.w;
#pragma unroll
            for (int o = 16; o > 0; o >>= 1) {
                s += __shfl_xor_sync(0xffffffffu, s, o);
                ss += __shfl_xor_sync(0xffffffffu, ss, o);
            }
            float m = s * (1.f / 128.f);
            float var = ss * (1.f / 128.f) - m * m;
            float inv = rsqrtf(var + 1e-5f);
            float4 g = ((const float4*)lng)[lane];
            float4 bb = ((const float4*)lnb)[lane];
            float4 y;
            y.x = (x.x - m) * inv * g.x + bb.x;
            y.y = (x.y - m) * inv * g.y + bb.y;
            y.z = (x.z - m) * inv * g.z + bb.z;
            y.w = (x.w - m) * inv * g.w + bb.w;
            ((float4*)(d_ef + (size_t)ge * CZ))[lane] = y;
        }
    }
}

// ---------------- generic 64x128 tf32 MMA tile -----------------------------------
template <bool SIG>
__device__ __forceinline__ void mma_tile(
    const float* __restrict__ Ag, const float* __restrict__ W, int wstride,
    const float* __restrict__ bias, float* __restrict__ dst, int eb) {
    extern __shared__ float sm[];
    float* As = sm;
    float* Bs = sm + 64 * 132;
    int t = threadIdx.x;

    const float* Asrc = Ag + (size_t)eb * 64 * CZ;
#pragma unroll
    for (int j = 0; j < 8; j++) {
        int idx = t + j * 256;
        int r = idx >> 5;
        int c4 = (idx & 31) * 4;
        float4 v = *(const float4*)(Asrc + r * CZ + c4);
        v.x = tf32r(v.x); v.y = tf32r(v.y); v.z = tf32r(v.z); v.w = tf32r(v.w);
        *(float4*)&As[r * 132 + c4] = v;
    }
#pragma unroll
    for (int j = 0; j < 16; j++) {
        int idx = t + j * 256;
        int r = idx >> 5;
        int c4 = (idx & 31) * 4;
        float4 v = *(const float4*)(W + (size_t)r * wstride + c4);
        v.x = tf32r(v.x); v.y = tf32r(v.y); v.z = tf32r(v.z); v.w = tf32r(v.w);
        *(float4*)&Bs[r * 132 + c4] = v;
    }
    __syncthreads();

    int warp = t >> 5, lane = t & 31;
    int g = lane >> 2, tid = lane & 3;
    int wm = warp >> 2, wn = warp & 3;

    float c[2][4][4];
#pragma unroll
    for (int mf = 0; mf < 2; mf++)
#pragma unroll
        for (int nf = 0; nf < 4; nf++)
#pragma unroll
            for (int i = 0; i < 4; i++) c[mf][nf][i] = 0.f;

    const unsigned* Au = (const unsigned*)As;
    const unsigned* Bu = (const unsigned*)Bs;

#pragma unroll
    for (int s = 0; s < 16; s++) {
        int k0 = s * 8;
        unsigned a[2][4];
#pragma unroll
        for (int mf = 0; mf < 2; mf++) {
            int rb = (wm * 32 + mf * 16 + g) * 132 + k0 + tid;
            a[mf][0] = Au[rb];
            a[mf][1] = Au[rb + 8 * 132];
            a[mf][2] = Au[rb + 4];
            a[mf][3] = Au[rb + 8 * 132 + 4];
        }
        unsigned b[4][2];
#pragma unroll
        for (int nf = 0; nf < 4; nf++) {
            int rb = (k0 + tid) * 132 + wn * 32 + nf * 8 + g;
            b[nf][0] = Bu[rb];
            b[nf][1] = Bu[rb + 4 * 132];
        }
#pragma unroll
        for (int mf = 0; mf < 2; mf++)
#pragma unroll
            for (int nf = 0; nf < 4; nf++)
                asm volatile(
                    "mma.sync.aligned.m16n8k8.row.col.f32.tf32.tf32.f32 "
                    "{%0,%1,%2,%3}, {%4,%5,%6,%7}, {%8,%9}, {%0,%1,%2,%3};"
                    : "+f"(c[mf][nf][0]), "+f"(c[mf][nf][1]),
                      "+f"(c[mf][nf][2]), "+f"(c[mf][nf][3])
                    : "r"(a[mf][0]), "r"(a[mf][1]), "r"(a[mf][2]), "r"(a[mf][3]),
                      "r"(b[nf][0]), "r"(b[nf][1]));
    }

#pragma unroll
    for (int nf = 0; nf < 4; nf++) {
        int col = wn * 32 + nf * 8 + tid * 2;
        float2 bi = *(const float2*)(bias + col);
#pragma unroll
        for (int mf = 0; mf < 2; mf++) {
            int row0 = eb * 64 + wm * 32 + mf * 16 + g;
            float x0 = c[mf][nf][0] + bi.x, x1 = c[mf][nf][1] + bi.y;
            float x2 = c[mf][nf][2] + bi.x, x3 = c[mf][nf][3] + bi.y;
            if (SIG) {
                x0 = 1.f / (1.f + __expf(-x0));
                x1 = 1.f / (1.f + __expf(-x1));
                x2 = 1.f / (1.f + __expf(-x2));
                x3 = 1.f / (1.f + __expf(-x3));
            }
            *(float2*)(dst + (size_t)row0 * CZ + col) = make_float2(x0, x1);
            *(float2*)(dst + (size_t)(row0 + 8) * CZ + col) = make_float2(x2, x3);
        }
    }
}

// ---------------- K2: q/k/v/og projections ---------------------------------------
__global__ __launch_bounds__(256) void k_proj_mma(
    const float* __restrict__ Wq, const float* __restrict__ bq,
    const float* __restrict__ Wkv, const float* __restrict__ bkv,
    const float* __restrict__ Wog, const float* __restrict__ bog) {
    int y = blockIdx.y;
    if (y == 0)      mma_tile<false>(d_ef, Wq, 128, bq, d_q, blockIdx.x);
    else if (y == 1) mma_tile<false>(d_ef, Wkv, 256, bkv, d_k, blockIdx.x);
    else if (y == 2) mma_tile<false>(d_ef, Wkv + 128, 256, bkv + 128, d_v, blockIdx.x);
    else             mma_tile<true>(d_ef, Wog, 128, bog, d_og, blockIdx.x);
}

// ---------------- K5: output projection -------------------------------------------
__global__ __launch_bounds__(256) void k_out_mma(
    const float* __restrict__ Wout, const float* __restrict__ bout,
    float* __restrict__ out) {
    mma_tile<false>(d_gupd, Wout, 128, bout, out, blockIdx.x);
}

// ---------------- K3: per-pair bias + attention logits -----------------------------
// MIO diet: gate nl via per-warp smem (LDS.128) instead of 64 SHFL/iter;
// 11-shuffle 4-head reduction instead of 20.
__global__ __launch_bounds__(256, 2) void k_pair(
    const float* __restrict__ trans,
    const float* __restrict__ Wbg, const float* __restrict__ bbg,
    const float* __restrict__ Wtb) {
    __shared__ float s_B[CG][CZ];     // 8 KB
    __shared__ float s_nl[8][4][16];  // 2 KB, per-warp nl staging
    __shared__ float s_nr[CG];
    int n2 = blockIdx.x, t = threadIdx.x;
    if (t < CG) s_nr[t] = d_nr[n2 * CG + t];
    __syncthreads();
    {
        int c = t & 127, half = t >> 7;
#pragma unroll
        for (int i = half * 8; i < half * 8 + 8; i++) {
            float a = 0.f;
#pragma unroll
            for (int j = 0; j < CG; j++) a += s_nr[j] * Wbg[(i * CG + j) * CZ + c];
            s_B[i][c] = a;
        }
    }
    __syncthreads();

    int warp = t >> 5, lane = t & 31;
    int c0 = lane * 4;
    int hb = lane >> 3;
    int hq = lane & 3;   // head this lane finalizes in the reduction
    ull bbg0 = *(const ull*)(bbg + c0);
    ull bbg1 = *(const ull*)(bbg + c0 + 2);
    float4 wtb0 = *(const float4*)(Wtb + (c0 + 0) * NH);
    float4 wtb1 = *(const float4*)(Wtb + (c0 + 1) * NH);
    float4 wtb2 = *(const float4*)(Wtb + (c0 + 2) * NH);
    float4 wtb3 = *(const float4*)(Wtb + (c0 + 3) * NH);
    float trx = trans[n2 * 3], try_ = trans[n2 * 3 + 1], trz = trans[n2 * 3 + 2];
    int beg = n2 * CAP2, end = beg + d_cnt2[n2];
    const float SCALE = 0.088388347648318447f;

    for (int m0 = beg + warp * 4; m0 < end; m0 += 32) {
        int np = end - m0; np = np > 4 ? 4 : np;
        int e0a[4], e1a[4], n1a[4], sla[4];
#pragma unroll
        for (int p = 0; p < 4; p++) {
            if (p < np) {
                int4 r = d_rec[m0 + p];
                e0a[p] = r.x; e1a[p] = r.y; n1a[p] = r.z; sla[p] = r.w;
            } else { e0a[p] = 0; e1a[p] = 0; n1a[p] = 0; sla[p] = 0; }
        }

        // stage nl[16] for the 4 pairs into per-warp smem (lanes 0-3)
        __syncwarp();
        if (lane < 4) {
            const float4* np4 = (const float4*)(d_nl + (size_t)n1a[lane] * CG);
            float4 a0 = np4[0], a1 = np4[1], a2 = np4[2], a3 = np4[3];
            *(float4*)&s_nl[warp][lane][0]  = a0;
            *(float4*)&s_nl[warp][lane][4]  = a1;
            *(float4*)&s_nl[warp][lane][8]  = a2;
            *(float4*)&s_nl[warp][lane][12] = a3;
        }

        float frme = 0.f;
        int i0me = 0;
        if (lane < 4) {
            int n1 = n1a[lane];
            float dx = trans[n1 * 3] - trx + 1e-8f;
            float dy = trans[n1 * 3 + 1] - try_ + 1e-8f;
            float dz = trans[n1 * 3 + 2] - trz + 1e-8f;
            float u = sqrtf(dx * dx + dy * dy + dz * dz) * LUT_SCALE;
            int i0 = (int)u;
            i0 = i0 > (LUT_N - 2) ? (LUT_N - 2) : i0;
            frme = u - (float)i0;
            i0me = i0;
        }
        __syncwarp();

        float db[4][4], qk[4];
#pragma unroll
        for (int p = 0; p < 4; p++) {
            float fr = __shfl_sync(0xffffffffu, frme, p);
            int i0 = __shfl_sync(0xffffffffu, i0me, p);
            float4 l0 = *(const float4*)(d_lut + (size_t)i0 * CZ + c0);
            float4 l1 = *(const float4*)(d_lut + (size_t)(i0 + 1) * CZ + c0);
            db[p][0] = l0.x + fr * (l1.x - l0.x);
            db[p][1] = l0.y + fr * (l1.y - l0.y);
            db[p][2] = l0.z + fr * (l1.z - l0.z);
            db[p][3] = l0.w + fr * (l1.w - l0.w);
            float4 q4 = *(const float4*)(d_q + (size_t)e1a[p] * CZ + c0);
            float4 k4 = *(const float4*)(d_k + (size_t)e0a[p] * CZ + c0);
            qk[p] = (q4.x * k4.x + q4.y * k4.y + q4.z * k4.z + q4.w * k4.w) * SCALE;
        }

        ull g0[4], g1[4];
#pragma unroll
        for (int p = 0; p < 4; p++) { g0[p] = bbg0; g1[p] = bbg1; }
#pragma unroll
        for (int ib = 0; ib < CG; ib += 4) {
            float4 nl4[4];
#pragma unroll
            for (int p = 0; p < 4; p++)
                nl4[p] = *(const float4*)&s_nl[warp][p][ib];
#pragma unroll
            for (int di = 0; di < 4; di++) {
                int i = ib + di;
                ull b0 = *(const ull*)&s_B[i][c0];
                ull b1 = *(const ull*)&s_B[i][c0 + 2];
#pragma unroll
                for (int p = 0; p < 4; p++) {
                    float nli = (di == 0) ? nl4[p].x : (di == 1) ? nl4[p].y
                               : (di == 2) ? nl4[p].z : nl4[p].w;
                    ull nd = pkdup(nli);
                    g0[p] = ffma2(nd, b0, g0[p]);
                    g1[p] = ffma2(nd, b1, g1[p]);
                }
            }
        }

#pragma unroll
        for (int p = 0; p < 4; p++) {
            if (p >= np) break;
            float ga, gb, gc, gd;
            upk2(g0[p], ga, gb);
            upk2(g1[p], gc, gd);
            float tv0 = db[p][0] * sigmoid_fast(ga);
            float tv1 = db[p][1] * sigmoid_fast(gb);
            float tv2 = db[p][2] * sigmoid_fast(gc);
            float tv3 = db[p][3] * sigmoid_fast(gd);

            float v0 = tv0 * wtb0.x + tv1 * wtb1.x + tv2 * wtb2.x + tv3 * wtb3.x;
            float v1 = tv0 * wtb0.y + tv1 * wtb1.y + tv2 * wtb2.y + tv3 * wtb3.y;
            float v2 = tv0 * wtb0.z + tv1 * wtb1.z + tv2 * wtb2.z + tv3 * wtb3.z;
            float v3 = tv0 * wtb0.w + tv1 * wtb1.w + tv2 * wtb2.w + tv3 * wtb3.w;
            v0 += (hb == 0) ? qk[p] : 0.f;
            v1 += (hb == 1) ? qk[p] : 0.f;
            v2 += (hb == 2) ? qk[p] : 0.f;
            v3 += (hb == 3) ? qk[p] : 0.f;
            // 11-op reduction: {1,2} per head, head-select, {4,8,16}
#pragma unroll
            for (int o = 1; o <= 2; o <<= 1) {
                v0 += __shfl_xor_sync(0xffffffffu, v0, o);
                v1 += __shfl_xor_sync(0xffffffffu, v1, o);
                v2 += __shfl_xor_sync(0xffffffffu, v2, o);
                v3 += __shfl_xor_sync(0xffffffffu, v3, o);
            }
            float y = (hq == 0) ? v0 : (hq == 1) ? v1 : (hq == 2) ? v2 : v3;
#pragma unroll
            for (int o = 4; o <= 16; o <<= 1)
                y += __shfl_xor_sync(0xffffffffu, y, o);
            if (lane < 4)
                d_attn[(size_t)sla[p] * 4 + lane] = __expf(y);
        }
    }
}

// ---------------- K4: segment softmax (pre-exp'd) + V agg + out gate ---------------
__global__ __launch_bounds__(256) void k_soft() {
    int warp = threadIdx.x >> 5, lane = threadIdx.x & 31;
    int tgt = blockIdx.x * 8 + warp;
    if (tgt >= E_EDGES) return;
    int beg = tgt * CAP1, end = beg + d_cnt[tgt];
    int hb = lane >> 3;
    int c0 = lane * 4;

    float sum = 0.f;
    float ax = 0.f, ay = 0.f, az = 0.f, aw = 0.f;
    float a_n = 0.f;
    int s_n = 0;
    if (beg < end) { a_n = d_attn[(size_t)beg * 4 + hb]; s_n = d_src[beg]; }
    for (int m = beg; m < end; m++) {
        float pp = a_n;
        int s = s_n;
        if (m + 1 < end) { a_n = d_attn[(size_t)(m + 1) * 4 + hb]; s_n = d_src[m + 1]; }
        sum += pp;
        float4 v = *(const float4*)(d_v + (size_t)s * CZ + c0);
        ax += pp * v.x; ay += pp * v.y; az += pp * v.z; aw += pp * v.w;
    }
    float inv = 1.f / (sum + 1e-16f);
    float4 og = *(const float4*)(d_og + (size_t)tgt * CZ + c0);
    float4 r = make_float4(ax * inv * og.x, ay * inv * og.y,
                           az * inv * og.z, aw * inv * og.w);
    *(float4*)(d_gupd + (size_t)tgt * CZ + c0) = r;
}

// ---------------- launch ------------------------------------------------------------
extern "C" void kernel_launch(void* const* d_in, const int* in_sizes, int n_in,
                              void* d_out, int out_size) {
    const float* node_features = (const float*)d_in[0];
    const float* node_trans    = (const float*)d_in[1];
    const float* edge_features = (const float*)d_in[2];
    const int*   edge_index    = (const int*)d_in[3];
    const int*   ee_index      = (const int*)d_in[4];
    const float* ln_g  = (const float*)d_in[5];
    const float* ln_b  = (const float*)d_in[6];
    const float* W_nl  = (const float*)d_in[7];
    const float* b_nl  = (const float*)d_in[8];
    const float* W_nr  = (const float*)d_in[9];
    const float* b_nr  = (const float*)d_in[10];
    const float* W_bg  = (const float*)d_in[11];
    const float* b_bg  = (const float*)d_in[12];
    const float* W_db  = (const float*)d_in[13];
    const float* b_db  = (const float*)d_in[14];
    const float* W_tb  = (const float*)d_in[15];
    const float* W_q   = (const float*)d_in[16];
    const float* b_q   = (const float*)d_in[17];
    const float* W_kv  = (const float*)d_in[18];
    const float* b_kv  = (const float*)d_in[19];
    const float* W_og  = (const float*)d_in[20];
    const float* b_og  = (const float*)d_in[21];
    const float* W_out = (const float*)d_in[22];
    const float* b_out = (const float*)d_in[23];
    float* out = (float*)d_out;

    cudaFuncSetAttribute(k_proj_mma, cudaFuncAttributeMaxDynamicSharedMemorySize, MMA_SMEM);
    cudaFuncSetAttribute(k_out_mma, cudaFuncAttributeMaxDynamicSharedMemorySize, MMA_SMEM);

    k_init<<<64, 512>>>();                                                   // 0
    k_misc<<<3200, 256>>>(node_features, W_nl, b_nl, W_nr, b_nr,             // 1
                          edge_index, ee_index, W_db, b_db,
                          edge_features, ln_g, ln_b);
    k_proj_mma<<<dim3(E_EDGES / 64, 4), 256, MMA_SMEM>>>(                    // 2
        W_q, b_q, W_kv, b_kv, W_og, b_og);
    k_pair<<<N_NODES, 256>>>(node_trans, W_bg, b_bg, W_tb);                  // 3 (ncu slot)
    k_soft<<<E_EDGES / 8, 256>>>();                                          // 4
    k_out_mma<<<E_EDGES / 64, 256, MMA_SMEM>>>(W_out, b_out, out);           // 5
}